// round 15
// baseline (speedup 1.0000x reference)
#include <cuda_runtime.h>
#include <cuda_bf16.h>
#include <cstdint>
#include <math.h>

// Problem: B=4, H=8, L=2048, DK=DV=32
#define LQ    2048
#define DKV   32
#define NBH   32
#define SCALE 0.17677669529663687f   // 1/sqrt(32)

// ---- bf16-split K/V scratch (16 MB total, static device globals) ----
__device__ __align__(16) __nv_bfloat16 g_KH[NBH][LQ][DKV];   // [bh][k][d]
__device__ __align__(16) __nv_bfloat16 g_KL[NBH][LQ][DKV];
__device__ __align__(16) __nv_bfloat16 g_VTH[NBH][DKV][LQ];  // [bh][v][k]
__device__ __align__(16) __nv_bfloat16 g_VTL[NBH][DKV][LQ];

// ---- dynamic smem layout (bytes) ----
// QH 0..10240, QL 10240..20480  (128 rows x 80B)
// stage s at 20480 + s*19456:  KH +0 (64x80), KL +5120, VTH +10240 (32x144), VTL +14848
#define QH_OFF    0
#define QL_OFF    10240
#define STG_BASE  20480
#define STG_SIZE  19456
#define SKH       0
#define SKL       5120
#define SVTH      10240
#define SVTL      14848
#define SMEM_BYTES (STG_BASE + 2 * STG_SIZE)   // 59392

__device__ __forceinline__ uint32_t smem_u32(const void* p) {
    uint32_t a;
    asm("{ .reg .u64 t; cvta.to.shared.u64 t, %1; cvt.u32.u64 %0, t; }" : "=r"(a) : "l"(p));
    return a;
}
__device__ __forceinline__ uint32_t bf2(float lo, float hi) {
    uint32_t r; asm("cvt.rn.bf16x2.f32 %0, %1, %2;" : "=r"(r) : "f"(hi), "f"(lo)); return r;
}
__device__ __forceinline__ float bf_lo(uint32_t u) { return __uint_as_float(u << 16); }
__device__ __forceinline__ float bf_hi(uint32_t u) { return __uint_as_float(u & 0xFFFF0000u); }

__device__ __forceinline__ void split8(const float* x, uint4& H, uint4& L) {
    uint32_t h[4], l[4];
#pragma unroll
    for (int i = 0; i < 4; ++i) {
        h[i] = bf2(x[2*i], x[2*i+1]);
        l[i] = bf2(x[2*i] - bf_lo(h[i]), x[2*i+1] - bf_hi(h[i]));
    }
    H = make_uint4(h[0], h[1], h[2], h[3]);
    L = make_uint4(l[0], l[1], l[2], l[3]);
}

__device__ __forceinline__ void ldsm4(uint32_t* r, uint32_t addr) {
    asm volatile("ldmatrix.sync.aligned.m8n8.x4.shared.b16 {%0,%1,%2,%3}, [%4];"
                 : "=r"(r[0]), "=r"(r[1]), "=r"(r[2]), "=r"(r[3]) : "r"(addr));
}
__device__ __forceinline__ uint32_t lm_addr(uint32_t base, int row0, int strideB,
                                            int colB, int lane) {
    return base + (uint32_t)((row0 + (lane & 15)) * strideB + colB + ((lane >> 4) << 4));
}
__device__ __forceinline__ void mma16816(float* d, const uint32_t* a,
                                         uint32_t b0, uint32_t b1) {
    asm volatile("mma.sync.aligned.m16n8k16.row.col.f32.bf16.bf16.f32 "
                 "{%0,%1,%2,%3}, {%4,%5,%6,%7}, {%8,%9}, {%0,%1,%2,%3};"
                 : "+f"(d[0]), "+f"(d[1]), "+f"(d[2]), "+f"(d[3])
                 : "r"(a[0]), "r"(a[1]), "r"(a[2]), "r"(a[3]), "r"(b0), "r"(b1));
}
__device__ __forceinline__ void pf_l2(const void* p) {
    asm volatile("prefetch.global.L2 [%0];" :: "l"(p));
}
__device__ __forceinline__ void cp16(uint32_t dst_smem, const void* src) {
    asm volatile("cp.async.ca.shared.global [%0], [%1], 16;"
                 :: "r"(dst_smem), "l"(src) : "memory");
}
#define CP_COMMIT() asm volatile("cp.async.commit_group;" ::: "memory")
#define CP_WAIT1()  asm volatile("cp.async.wait_group 1;" ::: "memory")
#define CP_WAIT0()  asm volatile("cp.async.wait_group 0;" ::: "memory")

// =================== pre-kernel: bf16-split conversion ===================
__global__ __launch_bounds__(256)
void convert_kv_kernel(const float* __restrict__ K, const float* __restrict__ V)
{
    const int bh  = blockIdx.x;
    const int tid = threadIdx.x;
    const float* Kg = K + (size_t)bh * LQ * DKV;
    const float* Vg = V + (size_t)bh * LQ * DKV;

    // K: layout-preserving split, fully coalesced
    uint4* kh = reinterpret_cast<uint4*>(&g_KH[bh][0][0]);
    uint4* kl = reinterpret_cast<uint4*>(&g_KL[bh][0][0]);
#pragma unroll 4
    for (int it = 0; it < (LQ * DKV) / (256 * 8); ++it) {   // 32 iters
        const int c = it * 256 + tid;                        // 8-elem chunk id
        float x[8];
        float4 a = *reinterpret_cast<const float4*>(Kg + c * 8);
        float4 b = *reinterpret_cast<const float4*>(Kg + c * 8 + 4);
        x[0]=a.x; x[1]=a.y; x[2]=a.z; x[3]=a.w; x[4]=b.x; x[5]=b.y; x[6]=b.z; x[7]=b.w;
        uint4 H, L; split8(x, H, L);
        kh[c] = H; kl[c] = L;
    }

    // V: transpose to [v][k]; writes coalesced (consecutive tid -> consecutive 16B)
    const int v  = tid >> 3;       // 0..31
    const int ch = tid & 7;        // 0..7
#pragma unroll 4
    for (int it = 0; it < LQ / 64; ++it) {   // 32 iters
        const int k0 = it * 64 + ch * 8;
        float x[8];
#pragma unroll
        for (int j = 0; j < 8; ++j) x[j] = Vg[(size_t)(k0 + j) * DKV + v];
        uint4 H, L; split8(x, H, L);
        *reinterpret_cast<uint4*>(&g_VTH[bh][v][k0]) = H;
        *reinterpret_cast<uint4*>(&g_VTL[bh][v][k0]) = L;
    }
}

// =================== main kernel ===================
__global__ __launch_bounds__(256, 2)
void sdpa_hmma_kernel(const float* __restrict__ Qg_,
                      const int*   __restrict__ Mg_,
                      const float* __restrict__ Rg_,
                      float* __restrict__ ctx_out,
                      float* __restrict__ sc_out)
{
    extern __shared__ __align__(16) char SM[];
    const uint32_t sb   = smem_u32(SM);
    const int tid  = threadIdx.x;
    const int wid  = tid >> 5;
    const int lane = tid & 31;
    const int qb   = blockIdx.x;     // 0..15
    const int bh   = blockIdx.y;     // 0..31

    const float* Qg = Qg_ + (size_t)bh * LQ * DKV + (size_t)qb * 128 * DKV;

    // per-thread row/col bases in score space
    const int rowg = qb * 128 + 16 * wid + (lane >> 2);   // q rows rowg, rowg+8
    const int cb   = 2 * (lane & 3);
    const float* R0 = Rg_ + (size_t)bh * LQ * LQ + (size_t)rowg * LQ + cb;
    const float* R1 = R0 + 8 * LQ;
    const int*   M0 = Mg_ + (size_t)bh * LQ * LQ + (size_t)rowg * LQ + cb;
    const int*   M1 = M0 + 8 * LQ;
    float*       S0 = sc_out + (size_t)bh * LQ * LQ + (size_t)rowg * LQ + cb;
    float*       S1 = S0 + 8 * LQ;

    // ---- cp.async tile loader: 4x16B per thread ----
    const int kr  = tid >> 2,  kc  = tid & 3;   // KH/KL: row 0..63, chunk 0..3
    const int vv  = tid >> 3,  vch = tid & 7;   // VTH/VTL: v 0..31, chunk 0..7
    auto load_tile = [&](int stage, int kb) {
        const uint32_t stg = sb + STG_BASE + stage * STG_SIZE;
        cp16(stg + SKH  + kr * 80  + kc * 16,  &g_KH[bh][kb * 64 + kr][kc * 8]);
        cp16(stg + SKL  + kr * 80  + kc * 16,  &g_KL[bh][kb * 64 + kr][kc * 8]);
        cp16(stg + SVTH + vv * 144 + vch * 16, &g_VTH[bh][vv][kb * 64 + vch * 8]);
        cp16(stg + SVTL + vv * 144 + vch * 16, &g_VTL[bh][vv][kb * 64 + vch * 8]);
    };

    // ---- cooperative Q store: [q][d] bf16 hi/lo, row stride 80B ----
    {
        const int r  = tid >> 1;
        const int c0 = (tid & 1) * 16;
        const float* qg = Qg + r * DKV + c0;
        float x[16];
#pragma unroll
        for (int t = 0; t < 4; ++t) {
            float4 a = *reinterpret_cast<const float4*>(qg + t * 4);
            x[t*4+0]=a.x; x[t*4+1]=a.y; x[t*4+2]=a.z; x[t*4+3]=a.w;
        }
#pragma unroll
        for (int half = 0; half < 2; ++half) {
            uint4 H, L; split8(x + half * 8, H, L);
            *reinterpret_cast<uint4*>(SM + QH_OFF + r * 80 + (c0 + half * 8) * 2) = H;
            *reinterpret_cast<uint4*>(SM + QL_OFF + r * 80 + (c0 + half * 8) * 2) = L;
        }
    }
    // kick off tile 0 and warm L2 for halves 0,1 of R/M
    load_tile(0, 0);
    CP_COMMIT();
    if ((lane & 3) == 0) {
        pf_l2(R0);      pf_l2(R1);      pf_l2(M0);      pf_l2(M1);
        pf_l2(R0 + 32); pf_l2(R1 + 32); pf_l2(M0 + 32); pf_l2(M1 + 32);
    }

    uint32_t aH[2][4], aL[2][4];
    float oacc[4][4];
    float lacc0 = 0.f, lacc1 = 0.f;
#pragma unroll
    for (int t = 0; t < 4; ++t)
#pragma unroll
        for (int i = 0; i < 4; ++i) oacc[t][i] = 0.f;

    for (int kb = 0; kb < LQ / 64; ++kb) {
        // issue next tile's loads, then wait for current tile
        if (kb + 1 < LQ / 64) {
            load_tile((kb + 1) & 1, kb + 1);
            CP_COMMIT();
            CP_WAIT1();
        } else {
            CP_WAIT0();
        }
        __syncthreads();   // tile kb visible to all warps

        const uint32_t stg = sb + STG_BASE + (kb & 1) * STG_SIZE;

        if (kb == 0) {   // Q fragments
#pragma unroll
            for (int ds = 0; ds < 2; ++ds) {
                ldsm4(aH[ds], lm_addr(sb + QH_OFF, 16 * wid, 80, 32 * ds, lane));
                ldsm4(aL[ds], lm_addr(sb + QL_OFF, 16 * wid, 80, 32 * ds, lane));
            }
        }

#pragma unroll
        for (int h = 0; h < 2; ++h) {
            const int hh = 2 * kb + h;

            // ---- L2 prefetch two halves ahead for R/M ----
            if ((lane & 3) == 0 && hh + 2 < 2 * (LQ / 64)) {
                const int noff = (hh + 2) * 32;
                pf_l2(R0 + noff); pf_l2(R1 + noff);
                pf_l2(M0 + noff); pf_l2(M1 + noff);
            }

            // ---- S = Q K^T for this 32-col half ----
            float sacc[4][4];
#pragma unroll
            for (int j = 0; j < 4; ++j)
#pragma unroll
                for (int i = 0; i < 4; ++i) sacc[j][i] = 0.f;

#pragma unroll
            for (int jpl = 0; jpl < 2; ++jpl) {
                const int jp = 2 * h + jpl;
#pragma unroll
                for (int ds = 0; ds < 2; ++ds) {
                    uint32_t kh[4], kl[4];
                    ldsm4(kh, lm_addr(stg + SKH, 16 * jp, 80, 32 * ds, lane));
                    ldsm4(kl, lm_addr(stg + SKL, 16 * jp, 80, 32 * ds, lane));
                    mma16816(sacc[2*jpl],   aH[ds], kh[0], kh[2]);
                    mma16816(sacc[2*jpl+1], aH[ds], kh[1], kh[3]);
                    mma16816(sacc[2*jpl],   aH[ds], kl[0], kl[2]);
                    mma16816(sacc[2*jpl+1], aH[ds], kl[1], kl[3]);
                    mma16816(sacc[2*jpl],   aL[ds], kh[0], kh[2]);
                    mma16816(sacc[2*jpl+1], aL[ds], kh[1], kh[3]);
                }
            }

            // ---- per 16-col slice: epilogue then PV immediately ----
#pragma unroll
            for (int sl = 0; sl < 2; ++sl) {
                const int s_abs = 2 * h + sl;
                const int col   = kb * 64 + 16 * s_abs;
                float p[2][4];
#pragma unroll
                for (int t = 0; t < 2; ++t) {
                    const int off = col + 8 * t;
                    const float2 ra = *reinterpret_cast<const float2*>(R0 + off);
                    const float2 rb = *reinterpret_cast<const float2*>(R1 + off);
                    const int2   ma = *reinterpret_cast<const int2*>(M0 + off);
                    const int2   mb = *reinterpret_cast<const int2*>(M1 + off);
                    const float* sc = sacc[2*sl + t];
                    float sv0 = ma.x ? -1e9f : fmaf(sc[0], SCALE, ra.x);
                    float sv1 = ma.y ? -1e9f : fmaf(sc[1], SCALE, ra.y);
                    float sv2 = mb.x ? -1e9f : fmaf(sc[2], SCALE, rb.x);
                    float sv3 = mb.y ? -1e9f : fmaf(sc[3], SCALE, rb.y);
                    *reinterpret_cast<float2*>(S0 + off) = make_float2(sv0, sv1);
                    *reinterpret_cast<float2*>(S1 + off) = make_float2(sv2, sv3);
                    p[t][0] = __expf(sv0); p[t][1] = __expf(sv1);
                    p[t][2] = __expf(sv2); p[t][3] = __expf(sv3);
                    lacc0 += p[t][0] + p[t][1];
                    lacc1 += p[t][2] + p[t][3];
                }
                uint32_t ph[4], pl[4];
                ph[0] = bf2(p[0][0], p[0][1]); ph[1] = bf2(p[0][2], p[0][3]);
                ph[2] = bf2(p[1][0], p[1][1]); ph[3] = bf2(p[1][2], p[1][3]);
                pl[0] = bf2(p[0][0] - bf_lo(ph[0]), p[0][1] - bf_hi(ph[0]));
                pl[1] = bf2(p[0][2] - bf_lo(ph[1]), p[0][3] - bf_hi(ph[1]));
                pl[2] = bf2(p[1][0] - bf_lo(ph[2]), p[1][1] - bf_hi(ph[2]));
                pl[3] = bf2(p[1][2] - bf_lo(ph[3]), p[1][3] - bf_hi(ph[3]));

#pragma unroll
                for (int vp = 0; vp < 2; ++vp) {
                    uint32_t vh[4], vl[4];
                    ldsm4(vh, lm_addr(stg + SVTH, 16 * vp, 144, 32 * s_abs, lane));
                    ldsm4(vl, lm_addr(stg + SVTL, 16 * vp, 144, 32 * s_abs, lane));
                    mma16816(oacc[2*vp],   ph, vh[0], vh[2]);
                    mma16816(oacc[2*vp+1], ph, vh[1], vh[3]);
                    mma16816(oacc[2*vp],   ph, vl[0], vl[2]);
                    mma16816(oacc[2*vp+1], ph, vl[1], vl[3]);
                    mma16816(oacc[2*vp],   pl, vh[0], vh[2]);
                    mma16816(oacc[2*vp+1], pl, vh[1], vh[3]);
                }
            }
        }
        __syncthreads();   // all warps done with tile kb's buffer
    }

    // ---- finalize: row sums across 4-lane col group, divide, store ----
    lacc0 += __shfl_xor_sync(0xffffffffu, lacc0, 1);
    lacc0 += __shfl_xor_sync(0xffffffffu, lacc0, 2);
    lacc1 += __shfl_xor_sync(0xffffffffu, lacc1, 1);
    lacc1 += __shfl_xor_sync(0xffffffffu, lacc1, 2);
    const float inv0 = 1.0f / lacc0;
    const float inv1 = 1.0f / lacc1;

    float* C0 = ctx_out + (size_t)bh * LQ * DKV + (size_t)rowg * DKV + cb;
    float* C1 = C0 + 8 * DKV;
#pragma unroll
    for (int t = 0; t < 4; ++t) {
        *reinterpret_cast<float2*>(C0 + 8 * t) =
            make_float2(oacc[t][0] * inv0, oacc[t][1] * inv0);
        *reinterpret_cast<float2*>(C1 + 8 * t) =
            make_float2(oacc[t][2] * inv1, oacc[t][3] * inv1);
    }
}

extern "C" void kernel_launch(void* const* d_in, const int* in_sizes, int n_in,
                              void* d_out, int out_size)
{
    const float* Q    = (const float*)d_in[0];
    const float* K    = (const float*)d_in[1];
    const float* V    = (const float*)d_in[2];
    const int*   mask = (const int*)d_in[3];
    const float* res  = (const float*)d_in[4];

    float* ctx = (float*)d_out;                           // [B,H,L,DV]
    float* sc  = (float*)d_out + (size_t)NBH * LQ * DKV;  // [B,H,L,L]

    convert_kv_kernel<<<NBH, 256>>>(K, V);

    cudaFuncSetAttribute(sdpa_hmma_kernel,
                         cudaFuncAttributeMaxDynamicSharedMemorySize, SMEM_BYTES);
    dim3 grid(LQ / 128, NBH);
    sdpa_hmma_kernel<<<grid, 256, SMEM_BYTES>>>(Q, mask, res, ctx, sc);
}

// round 16
// speedup vs baseline: 1.0531x; 1.0531x over previous
#include <cuda_runtime.h>
#include <cuda_bf16.h>
#include <cstdint>
#include <math.h>

// Problem: B=4, H=8, L=2048, DK=DV=32
#define LQ    2048
#define DKV   32
#define NBH   32
#define SCALE 0.17677669529663687f   // 1/sqrt(32)

// ---- bf16-split K/V scratch (16 MB total, static device globals) ----
__device__ __align__(16) __nv_bfloat16 g_KH[NBH][LQ][DKV];   // [bh][k][d]
__device__ __align__(16) __nv_bfloat16 g_KL[NBH][LQ][DKV];
__device__ __align__(16) __nv_bfloat16 g_VTH[NBH][DKV][LQ];  // [bh][v][k]
__device__ __align__(16) __nv_bfloat16 g_VTL[NBH][DKV][LQ];

// ---- dynamic smem layout (bytes) ----
// QH 0..10240, QL 10240..20480  (128 rows x 80B)
// stage s at 20480 + s*19456:  KH +0 (64x80), KL +5120, VTH +10240 (32x144), VTL +14848
#define QH_OFF    0
#define QL_OFF    10240
#define STG_BASE  20480
#define STG_SIZE  19456
#define SKH       0
#define SKL       5120
#define SVTH      10240
#define SVTL      14848
#define SMEM_BYTES (STG_BASE + 2 * STG_SIZE)   // 59392

__device__ __forceinline__ uint32_t smem_u32(const void* p) {
    uint32_t a;
    asm("{ .reg .u64 t; cvta.to.shared.u64 t, %1; cvt.u32.u64 %0, t; }" : "=r"(a) : "l"(p));
    return a;
}
__device__ __forceinline__ uint32_t bf2(float lo, float hi) {
    uint32_t r; asm("cvt.rn.bf16x2.f32 %0, %1, %2;" : "=r"(r) : "f"(hi), "f"(lo)); return r;
}
__device__ __forceinline__ float bf_lo(uint32_t u) { return __uint_as_float(u << 16); }
__device__ __forceinline__ float bf_hi(uint32_t u) { return __uint_as_float(u & 0xFFFF0000u); }

__device__ __forceinline__ void split8(const float* x, uint4& H, uint4& L) {
    uint32_t h[4], l[4];
#pragma unroll
    for (int i = 0; i < 4; ++i) {
        h[i] = bf2(x[2*i], x[2*i+1]);
        l[i] = bf2(x[2*i] - bf_lo(h[i]), x[2*i+1] - bf_hi(h[i]));
    }
    H = make_uint4(h[0], h[1], h[2], h[3]);
    L = make_uint4(l[0], l[1], l[2], l[3]);
}

__device__ __forceinline__ void ldsm4(uint32_t* r, uint32_t addr) {
    asm volatile("ldmatrix.sync.aligned.m8n8.x4.shared.b16 {%0,%1,%2,%3}, [%4];"
                 : "=r"(r[0]), "=r"(r[1]), "=r"(r[2]), "=r"(r[3]) : "r"(addr));
}
__device__ __forceinline__ uint32_t lm_addr(uint32_t base, int row0, int strideB,
                                            int colB, int lane) {
    return base + (uint32_t)((row0 + (lane & 15)) * strideB + colB + ((lane >> 4) << 4));
}
__device__ __forceinline__ void mma16816(float* d, const uint32_t* a,
                                         uint32_t b0, uint32_t b1) {
    asm volatile("mma.sync.aligned.m16n8k16.row.col.f32.bf16.bf16.f32 "
                 "{%0,%1,%2,%3}, {%4,%5,%6,%7}, {%8,%9}, {%0,%1,%2,%3};"
                 : "+f"(d[0]), "+f"(d[1]), "+f"(d[2]), "+f"(d[3])
                 : "r"(a[0]), "r"(a[1]), "r"(a[2]), "r"(a[3]), "r"(b0), "r"(b1));
}
__device__ __forceinline__ void pf_l2(const void* p) {
    asm volatile("prefetch.global.L2 [%0];" :: "l"(p));
}
__device__ __forceinline__ void cp16(uint32_t dst_smem, const void* src) {
    asm volatile("cp.async.ca.shared.global [%0], [%1], 16;"
                 :: "r"(dst_smem), "l"(src) : "memory");
}
#define CP_COMMIT() asm volatile("cp.async.commit_group;" ::: "memory")
#define CP_WAIT1()  asm volatile("cp.async.wait_group 1;" ::: "memory")
#define CP_WAIT0()  asm volatile("cp.async.wait_group 0;" ::: "memory")

// =================== pre-kernel: bf16-split conversion ===================
// grid = (NBH, 8): 256 CTAs so the whole chip participates.
__global__ __launch_bounds__(256)
void convert_kv_kernel(const float* __restrict__ K, const float* __restrict__ V)
{
    const int bh  = blockIdx.x;
    const int seg = blockIdx.y;          // 0..7, covers 256 k-rows
    const int tid = threadIdx.x;
    const float* Kg = K + (size_t)bh * LQ * DKV;
    const float* Vg = V + (size_t)bh * LQ * DKV;

    // K: layout-preserving split, fully coalesced. 1024 8-elem chunks per segment.
    uint4* kh = reinterpret_cast<uint4*>(&g_KH[bh][0][0]);
    uint4* kl = reinterpret_cast<uint4*>(&g_KL[bh][0][0]);
#pragma unroll
    for (int it = 0; it < 4; ++it) {
        const int c = (seg * 4 + it) * 256 + tid;
        float x[8];
        float4 a = *reinterpret_cast<const float4*>(Kg + c * 8);
        float4 b = *reinterpret_cast<const float4*>(Kg + c * 8 + 4);
        x[0]=a.x; x[1]=a.y; x[2]=a.z; x[3]=a.w; x[4]=b.x; x[5]=b.y; x[6]=b.z; x[7]=b.w;
        uint4 H, L; split8(x, H, L);
        kh[c] = H; kl[c] = L;
    }

    // V: transpose to [v][k] for this segment's 256 k-rows; writes coalesced.
    const int v  = tid >> 3;       // 0..31
    const int ch = tid & 7;        // 0..7
#pragma unroll
    for (int it = 0; it < 4; ++it) {
        const int k0 = seg * 256 + it * 64 + ch * 8;
        float x[8];
#pragma unroll
        for (int j = 0; j < 8; ++j) x[j] = Vg[(size_t)(k0 + j) * DKV + v];
        uint4 H, L; split8(x, H, L);
        *reinterpret_cast<uint4*>(&g_VTH[bh][v][k0]) = H;
        *reinterpret_cast<uint4*>(&g_VTL[bh][v][k0]) = L;
    }
}

// =================== main kernel (unchanged from R15) ===================
__global__ __launch_bounds__(256, 2)
void sdpa_hmma_kernel(const float* __restrict__ Qg_,
                      const int*   __restrict__ Mg_,
                      const float* __restrict__ Rg_,
                      float* __restrict__ ctx_out,
                      float* __restrict__ sc_out)
{
    extern __shared__ __align__(16) char SM[];
    const uint32_t sb   = smem_u32(SM);
    const int tid  = threadIdx.x;
    const int wid  = tid >> 5;
    const int lane = tid & 31;
    const int qb   = blockIdx.x;     // 0..15
    const int bh   = blockIdx.y;     // 0..31

    const float* Qg = Qg_ + (size_t)bh * LQ * DKV + (size_t)qb * 128 * DKV;

    // per-thread row/col bases in score space
    const int rowg = qb * 128 + 16 * wid + (lane >> 2);   // q rows rowg, rowg+8
    const int cb   = 2 * (lane & 3);
    const float* R0 = Rg_ + (size_t)bh * LQ * LQ + (size_t)rowg * LQ + cb;
    const float* R1 = R0 + 8 * LQ;
    const int*   M0 = Mg_ + (size_t)bh * LQ * LQ + (size_t)rowg * LQ + cb;
    const int*   M1 = M0 + 8 * LQ;
    float*       S0 = sc_out + (size_t)bh * LQ * LQ + (size_t)rowg * LQ + cb;
    float*       S1 = S0 + 8 * LQ;

    // ---- cp.async tile loader: 4x16B per thread ----
    const int kr  = tid >> 2,  kc  = tid & 3;   // KH/KL: row 0..63, chunk 0..3
    const int vv  = tid >> 3,  vch = tid & 7;   // VTH/VTL: v 0..31, chunk 0..7
    auto load_tile = [&](int stage, int kb) {
        const uint32_t stg = sb + STG_BASE + stage * STG_SIZE;
        cp16(stg + SKH  + kr * 80  + kc * 16,  &g_KH[bh][kb * 64 + kr][kc * 8]);
        cp16(stg + SKL  + kr * 80  + kc * 16,  &g_KL[bh][kb * 64 + kr][kc * 8]);
        cp16(stg + SVTH + vv * 144 + vch * 16, &g_VTH[bh][vv][kb * 64 + vch * 8]);
        cp16(stg + SVTL + vv * 144 + vch * 16, &g_VTL[bh][vv][kb * 64 + vch * 8]);
    };

    // ---- cooperative Q store: [q][d] bf16 hi/lo, row stride 80B ----
    {
        const int r  = tid >> 1;
        const int c0 = (tid & 1) * 16;
        const float* qg = Qg + r * DKV + c0;
        float x[16];
#pragma unroll
        for (int t = 0; t < 4; ++t) {
            float4 a = *reinterpret_cast<const float4*>(qg + t * 4);
            x[t*4+0]=a.x; x[t*4+1]=a.y; x[t*4+2]=a.z; x[t*4+3]=a.w;
        }
#pragma unroll
        for (int half = 0; half < 2; ++half) {
            uint4 H, L; split8(x + half * 8, H, L);
            *reinterpret_cast<uint4*>(SM + QH_OFF + r * 80 + (c0 + half * 8) * 2) = H;
            *reinterpret_cast<uint4*>(SM + QL_OFF + r * 80 + (c0 + half * 8) * 2) = L;
        }
    }
    // kick off tile 0 and warm L2 for halves 0,1 of R/M
    load_tile(0, 0);
    CP_COMMIT();
    if ((lane & 3) == 0) {
        pf_l2(R0);      pf_l2(R1);      pf_l2(M0);      pf_l2(M1);
        pf_l2(R0 + 32); pf_l2(R1 + 32); pf_l2(M0 + 32); pf_l2(M1 + 32);
    }

    uint32_t aH[2][4], aL[2][4];
    float oacc[4][4];
    float lacc0 = 0.f, lacc1 = 0.f;
#pragma unroll
    for (int t = 0; t < 4; ++t)
#pragma unroll
        for (int i = 0; i < 4; ++i) oacc[t][i] = 0.f;

    for (int kb = 0; kb < LQ / 64; ++kb) {
        // issue next tile's loads, then wait for current tile
        if (kb + 1 < LQ / 64) {
            load_tile((kb + 1) & 1, kb + 1);
            CP_COMMIT();
            CP_WAIT1();
        } else {
            CP_WAIT0();
        }
        __syncthreads();   // tile kb visible to all warps

        const uint32_t stg = sb + STG_BASE + (kb & 1) * STG_SIZE;

        if (kb == 0) {   // Q fragments
#pragma unroll
            for (int ds = 0; ds < 2; ++ds) {
                ldsm4(aH[ds], lm_addr(sb + QH_OFF, 16 * wid, 80, 32 * ds, lane));
                ldsm4(aL[ds], lm_addr(sb + QL_OFF, 16 * wid, 80, 32 * ds, lane));
            }
        }

#pragma unroll
        for (int h = 0; h < 2; ++h) {
            const int hh = 2 * kb + h;

            // ---- L2 prefetch two halves ahead for R/M ----
            if ((lane & 3) == 0 && hh + 2 < 2 * (LQ / 64)) {
                const int noff = (hh + 2) * 32;
                pf_l2(R0 + noff); pf_l2(R1 + noff);
                pf_l2(M0 + noff); pf_l2(M1 + noff);
            }

            // ---- S = Q K^T for this 32-col half ----
            float sacc[4][4];
#pragma unroll
            for (int j = 0; j < 4; ++j)
#pragma unroll
                for (int i = 0; i < 4; ++i) sacc[j][i] = 0.f;

#pragma unroll
            for (int jpl = 0; jpl < 2; ++jpl) {
                const int jp = 2 * h + jpl;
#pragma unroll
                for (int ds = 0; ds < 2; ++ds) {
                    uint32_t kh[4], kl[4];
                    ldsm4(kh, lm_addr(stg + SKH, 16 * jp, 80, 32 * ds, lane));
                    ldsm4(kl, lm_addr(stg + SKL, 16 * jp, 80, 32 * ds, lane));
                    mma16816(sacc[2*jpl],   aH[ds], kh[0], kh[2]);
                    mma16816(sacc[2*jpl+1], aH[ds], kh[1], kh[3]);
                    mma16816(sacc[2*jpl],   aH[ds], kl[0], kl[2]);
                    mma16816(sacc[2*jpl+1], aH[ds], kl[1], kl[3]);
                    mma16816(sacc[2*jpl],   aL[ds], kh[0], kh[2]);
                    mma16816(sacc[2*jpl+1], aL[ds], kh[1], kh[3]);
                }
            }

            // ---- per 16-col slice: epilogue then PV immediately ----
#pragma unroll
            for (int sl = 0; sl < 2; ++sl) {
                const int s_abs = 2 * h + sl;
                const int col   = kb * 64 + 16 * s_abs;
                float p[2][4];
#pragma unroll
                for (int t = 0; t < 2; ++t) {
                    const int off = col + 8 * t;
                    const float2 ra = *reinterpret_cast<const float2*>(R0 + off);
                    const float2 rb = *reinterpret_cast<const float2*>(R1 + off);
                    const int2   ma = *reinterpret_cast<const int2*>(M0 + off);
                    const int2   mb = *reinterpret_cast<const int2*>(M1 + off);
                    const float* sc = sacc[2*sl + t];
                    float sv0 = ma.x ? -1e9f : fmaf(sc[0], SCALE, ra.x);
                    float sv1 = ma.y ? -1e9f : fmaf(sc[1], SCALE, ra.y);
                    float sv2 = mb.x ? -1e9f : fmaf(sc[2], SCALE, rb.x);
                    float sv3 = mb.y ? -1e9f : fmaf(sc[3], SCALE, rb.y);
                    *reinterpret_cast<float2*>(S0 + off) = make_float2(sv0, sv1);
                    *reinterpret_cast<float2*>(S1 + off) = make_float2(sv2, sv3);
                    p[t][0] = __expf(sv0); p[t][1] = __expf(sv1);
                    p[t][2] = __expf(sv2); p[t][3] = __expf(sv3);
                    lacc0 += p[t][0] + p[t][1];
                    lacc1 += p[t][2] + p[t][3];
                }
                uint32_t ph[4], pl[4];
                ph[0] = bf2(p[0][0], p[0][1]); ph[1] = bf2(p[0][2], p[0][3]);
                ph[2] = bf2(p[1][0], p[1][1]); ph[3] = bf2(p[1][2], p[1][3]);
                pl[0] = bf2(p[0][0] - bf_lo(ph[0]), p[0][1] - bf_hi(ph[0]));
                pl[1] = bf2(p[0][2] - bf_lo(ph[1]), p[0][3] - bf_hi(ph[1]));
                pl[2] = bf2(p[1][0] - bf_lo(ph[2]), p[1][1] - bf_hi(ph[2]));
                pl[3] = bf2(p[1][2] - bf_lo(ph[3]), p[1][3] - bf_hi(ph[3]));

#pragma unroll
                for (int vp = 0; vp < 2; ++vp) {
                    uint32_t vh[4], vl[4];
                    ldsm4(vh, lm_addr(stg + SVTH, 16 * vp, 144, 32 * s_abs, lane));
                    ldsm4(vl, lm_addr(stg + SVTL, 16 * vp, 144, 32 * s_abs, lane));
                    mma16816(oacc[2*vp],   ph, vh[0], vh[2]);
                    mma16816(oacc[2*vp+1], ph, vh[1], vh[3]);
                    mma16816(oacc[2*vp],   ph, vl[0], vl[2]);
                    mma16816(oacc[2*vp+1], ph, vl[1], vl[3]);
                    mma16816(oacc[2*vp],   pl, vh[0], vh[2]);
                    mma16816(oacc[2*vp+1], pl, vh[1], vh[3]);
                }
            }
        }
        __syncthreads();   // all warps done with tile kb's buffer
    }

    // ---- finalize: row sums across 4-lane col group, divide, store ----
    lacc0 += __shfl_xor_sync(0xffffffffu, lacc0, 1);
    lacc0 += __shfl_xor_sync(0xffffffffu, lacc0, 2);
    lacc1 += __shfl_xor_sync(0xffffffffu, lacc1, 1);
    lacc1 += __shfl_xor_sync(0xffffffffu, lacc1, 2);
    const float inv0 = 1.0f / lacc0;
    const float inv1 = 1.0f / lacc1;

    float* C0 = ctx_out + (size_t)bh * LQ * DKV + (size_t)rowg * DKV + cb;
    float* C1 = C0 + 8 * DKV;
#pragma unroll
    for (int t = 0; t < 4; ++t) {
        *reinterpret_cast<float2*>(C0 + 8 * t) =
            make_float2(oacc[t][0] * inv0, oacc[t][1] * inv0);
        *reinterpret_cast<float2*>(C1 + 8 * t) =
            make_float2(oacc[t][2] * inv1, oacc[t][3] * inv1);
    }
}

extern "C" void kernel_launch(void* const* d_in, const int* in_sizes, int n_in,
                              void* d_out, int out_size)
{
    const float* Q    = (const float*)d_in[0];
    const float* K    = (const float*)d_in[1];
    const float* V    = (const float*)d_in[2];
    const int*   mask = (const int*)d_in[3];
    const float* res  = (const float*)d_in[4];

    float* ctx = (float*)d_out;                           // [B,H,L,DV]
    float* sc  = (float*)d_out + (size_t)NBH * LQ * DKV;  // [B,H,L,L]

    dim3 cgrid(NBH, 8);
    convert_kv_kernel<<<cgrid, 256>>>(K, V);

    cudaFuncSetAttribute(sdpa_hmma_kernel,
                         cudaFuncAttributeMaxDynamicSharedMemorySize, SMEM_BYTES);
    dim3 grid(LQ / 128, NBH);
    sdpa_hmma_kernel<<<grid, 256, SMEM_BYTES>>>(Q, mask, res, ctx, sc);
}